// round 13
// baseline (speedup 1.0000x reference)
#include <cuda_runtime.h>
#include <cuda_fp16.h>
#include <cstdint>

#define LLEN 2048
#define HH   8
#define EE   32
#define DD   32
#define NTHR 128
#define NSPLIT 4
#define L2E  1.4426950408889634f

// ---- pre-converted fp16 operand arrays (filled by pass-1 kernel) ----
__device__ __half g_Kh [16 * 2048 * 32];
__device__ __half g_Kph[16 * 2048 * 32];
__device__ __half g_Vh [16 * 2048 * 32];
__device__ __half g_lbh[16 * 2048];            // half(-||k'||^2/32 * log2(e))
// ---- split-S partial accumulators ----
__device__ float  g_O[NSPLIT][16 * 2048 * 32];
__device__ float  g_L[NSPLIT][16 * 2048];

struct Tile {                  // 80-byte row stride -> conflict-free ldmatrix
    __half K [64][40];
    __half Kp[64][40];
    __half Vh[64][40];
    __half lb[64];
};
#define SMEM_BYTES (2 * (int)sizeof(Tile))

__device__ __forceinline__ uint32_t smem_u32(const void* p) {
    uint32_t a;
    asm("{ .reg .u64 t; cvta.to.shared.u64 t, %1; cvt.u32.u64 %0, t; }"
        : "=r"(a) : "l"(p));
    return a;
}
__device__ __forceinline__ void cp16(uint32_t dst, const void* src) {
    asm volatile("cp.async.cg.shared.global [%0], [%1], 16;"
                 :: "r"(dst), "l"(src) : "memory");
}
#define CP_COMMIT() asm volatile("cp.async.commit_group;" ::: "memory")
#define CP_WAIT0()  asm volatile("cp.async.wait_group 0;" ::: "memory")

__device__ __forceinline__ void ldsm4(uint32_t* r, uint32_t a) {
    asm volatile("ldmatrix.sync.aligned.m8n8.x4.shared.b16 {%0,%1,%2,%3}, [%4];"
                 : "=r"(r[0]), "=r"(r[1]), "=r"(r[2]), "=r"(r[3]) : "r"(a));
}
__device__ __forceinline__ void ldsm4t(uint32_t* r, uint32_t a) {
    asm volatile("ldmatrix.sync.aligned.m8n8.x4.trans.shared.b16 {%0,%1,%2,%3}, [%4];"
                 : "=r"(r[0]), "=r"(r[1]), "=r"(r[2]), "=r"(r[3]) : "r"(a));
}
__device__ __forceinline__ void mma16816(float4& d, const uint32_t* a,
                                         uint32_t b0, uint32_t b1) {
    asm volatile(
        "mma.sync.aligned.m16n8k16.row.col.f32.f16.f16.f32 "
        "{%0,%1,%2,%3}, {%4,%5,%6,%7}, {%8,%9}, {%0,%1,%2,%3};"
        : "+f"(d.x), "+f"(d.y), "+f"(d.z), "+f"(d.w)
        : "r"(a[0]), "r"(a[1]), "r"(a[2]), "r"(a[3]), "r"(b0), "r"(b1));
}
__device__ __forceinline__ uint32_t pack2h(float x, float y) {
    __half2 h = __floats2half2_rn(x, y);
    return *reinterpret_cast<uint32_t*>(&h);
}
// ---- packed half2 epilogue ops ----
__device__ __forceinline__ uint32_t ex2h2(uint32_t x) {
    uint32_t r;
    asm("ex2.approx.f16x2 %0, %1;" : "=r"(r) : "r"(x));
    return r;
}
__device__ __forceinline__ uint32_t hadd2(uint32_t a, uint32_t b) {
    uint32_t r;
    asm("add.f16x2 %0, %1, %2;" : "=r"(r) : "r"(a), "r"(b));
    return r;
}
__device__ __forceinline__ uint32_t hmul2(uint32_t a, uint32_t b) {
    uint32_t r;
    asm("mul.f16x2 %0, %1, %2;" : "=r"(r) : "r"(a), "r"(b));
    return r;
}

// ========== pass 1: convert K, K', V to fp16 (8 threads per row) ==========
__global__ void __launch_bounds__(256)
preconvert(const float* __restrict__ kg, const float* __restrict__ vg)
{
    const int idx = blockIdx.x * 256 + threadIdx.x;   // 262144 threads
    const int rg  = idx >> 3;            // global row 0..32767
    const int j   = idx & 7;             // chunk within row
    const int r   = rg & 2047;
    const int bh  = rg >> 11;
    const int b   = bh >> 3, h = bh & 7;
    const float inv2 = 0.03125f;
    const size_t drow = (size_t)bh * LLEN + r;

    float4 tk = *(const float4*)(kg + ((size_t)(b * LLEN + r) * HH + h) * EE + 4 * j);
    const int rk = h * 256 + (r >> 3), hk = r & 7;
    float4 tp = *(const float4*)(kg + ((size_t)(b * LLEN + rk) * HH + hk) * EE + 4 * j);
    float4 tv = *(const float4*)(vg + ((size_t)(b * LLEN + r) * HH + h) * DD + 4 * j);

    *(uint2*)(g_Kh + drow * EE + 4 * j) =
        make_uint2(pack2h(tk.x, tk.y), pack2h(tk.z, tk.w));
    *(uint2*)(g_Kph + drow * EE + 4 * j) =
        make_uint2(pack2h(tp.x, tp.y), pack2h(tp.z, tp.w));
    float k2 = tp.x*tp.x + tp.y*tp.y + tp.z*tp.z + tp.w*tp.w;
    k2 += __shfl_xor_sync(0xffffffffu, k2, 1);
    k2 += __shfl_xor_sync(0xffffffffu, k2, 2);
    k2 += __shfl_xor_sync(0xffffffffu, k2, 4);
    if (j == 0) g_lbh[drow] = __float2half(-k2 * inv2 * L2E);
    *(uint2*)(g_Vh + drow * DD + 4 * j) =
        make_uint2(pack2h(tv.x, tv.y), pack2h(tv.z, tv.w));
}

// ================= main kernel (split-S, 4 CTAs per l-tile) =================
__global__ void __launch_bounds__(NTHR, 5)
gauss_attn_mma9(const float* __restrict__ qg)
{
    extern __shared__ Tile tiles[];   // [2]
    const int tid  = threadIdx.x;
    const int lane = tid & 31;
    const int wid  = tid >> 5;
    const int g    = lane >> 2;
    const int tg   = lane & 3;
    const int i8   = lane & 7;
    const int g4lo = (lane >> 3) & 1;
    const int g4hi = lane >> 4;

    const int bx    = blockIdx.x;               // 2048 CTAs
    const int bh    = bx & 15;
    const int split = (bx >> 4) & (NSPLIT - 1);
    const int u     = bx >> 6;
    const int lt    = (u & 1) ? (u >> 1) : (31 - (u >> 1));   // interleaved heavy/light
    const int b     = bh >> 3, h = bh & 7;
    const int l0    = lt * 64;
    const int nT    = lt + 1;

    const float inv2 = 0.03125f;                   // 1/32
    const float inv3 = 0.005524271728019903f;      // 32^-1.5

    const int r0g = l0 + wid * 16 + g;
    const int r1g = r0g + 8;
    const int rmaxW = l0 + wid * 16 + 15;

    // ---- incremental gmem pointers (start at tile `split`, advance 4 tiles) ----
    const int lr = tid >> 1, half = tid & 1;
    const size_t rowbase = ((size_t)bh * LLEN + split * 64 + lr) * EE + half * 16;
    const __half* kP  = g_Kh  + rowbase;
    const __half* kpP = g_Kph + rowbase;
    const __half* vhP = g_Vh  + rowbase;
    const __half* bP  = g_lbh + (size_t)bh * LLEN + split * 64 + tid * 8;

    if (split < nT) {
        Tile* tn = &tiles[0];
        cp16(smem_u32(&tn->K [lr][half*16]),   kP);
        cp16(smem_u32(&tn->K [lr][half*16+8]), kP  + 8);
        cp16(smem_u32(&tn->Kp[lr][half*16]),   kpP);
        cp16(smem_u32(&tn->Kp[lr][half*16+8]), kpP + 8);
        cp16(smem_u32(&tn->Vh[lr][half*16]),   vhP);
        cp16(smem_u32(&tn->Vh[lr][half*16+8]), vhP + 8);
        if (tid < 8) cp16(smem_u32(&tn->lb[tid*8]), bP);
        CP_COMMIT();
        kP += 8192; kpP += 8192; vhP += 8192; bP += 256;
    }

    // ---- Q / Q' fragments: q2 first, then pack fp16 ----
    uint32_t qA[2][4], pA_[2][4];
    float q2r0 = 0.f, q2r1 = 0.f;
    {
        const int lq0 = h * 256 + (r0g >> 3), hq0 = r0g & 7;
        const int lq1 = h * 256 + (r1g >> 3), hq1 = r1g & 7;
        const float* s0p = qg + ((size_t)(b * LLEN + lq0) * HH + hq0) * EE + 2 * tg;
        const float* s1p = qg + ((size_t)(b * LLEN + lq1) * HH + hq1) * EE + 2 * tg;
        float2 t;
        #pragma unroll
        for (int c = 0; c < 4; c++) {
            t = *(const float2*)(s0p + 8 * c);  q2r0 += t.x*t.x + t.y*t.y;
            t = *(const float2*)(s1p + 8 * c);  q2r1 += t.x*t.x + t.y*t.y;
        }
        q2r0 += __shfl_xor_sync(0xffffffffu, q2r0, 1);
        q2r0 += __shfl_xor_sync(0xffffffffu, q2r0, 2);
        q2r1 += __shfl_xor_sync(0xffffffffu, q2r1, 1);
        q2r1 += __shfl_xor_sync(0xffffffffu, q2r1, 2);
        const float al0 = __expf(-q2r0 * inv2);    // alpha = exp(-||q'||^2/32)
        const float al1 = __expf(-q2r1 * inv2);
        const float sc0 = inv3 * L2E * al0;        // scale*log2e*alpha folded into Q
        const float sc1 = inv3 * L2E * al1;
        const float cs  = inv2 * 2.f * L2E;        // 2*log2e/32 folded into Q'

        const float* p0 = qg + ((size_t)(b * LLEN + r0g) * HH + h) * EE + 2 * tg;
        const float* p1 = qg + ((size_t)(b * LLEN + r1g) * HH + h) * EE + 2 * tg;
        #pragma unroll
        for (int kk = 0; kk < 2; kk++) {
            t = *(const float2*)(p0 + 16*kk);      qA[kk][0] = pack2h(t.x*sc0, t.y*sc0);
            t = *(const float2*)(p1 + 16*kk);      qA[kk][1] = pack2h(t.x*sc1, t.y*sc1);
            t = *(const float2*)(p0 + 16*kk + 8);  qA[kk][2] = pack2h(t.x*sc0, t.y*sc0);
            t = *(const float2*)(p1 + 16*kk + 8);  qA[kk][3] = pack2h(t.x*sc1, t.y*sc1);
            t = *(const float2*)(s0p + 16*kk);     pA_[kk][0] = pack2h(t.x*cs, t.y*cs);
            t = *(const float2*)(s1p + 16*kk);     pA_[kk][1] = pack2h(t.x*cs, t.y*cs);
            t = *(const float2*)(s0p + 16*kk + 8); pA_[kk][2] = pack2h(t.x*cs, t.y*cs);
            t = *(const float2*)(s1p + 16*kk + 8); pA_[kk][3] = pack2h(t.x*cs, t.y*cs);
        }
    }
    const uint32_t ONESH = pack2h(1.f, 1.f);

    float4 O[4], O5;
    #pragma unroll
    for (int i = 0; i < 4; i++) O[i] = make_float4(0.f, 0.f, 0.f, 0.f);
    O5 = make_float4(0.f, 0.f, 0.f, 0.f);

    int it = 0;
    for (int t = split; t < nT; t += NSPLIT, it++) {
        const int cur = it & 1;
        CP_WAIT0();
        __syncthreads();
        if (t + NSPLIT < nT) {
            Tile* tn = &tiles[cur ^ 1];
            cp16(smem_u32(&tn->K [lr][half*16]),   kP);
            cp16(smem_u32(&tn->K [lr][half*16+8]), kP  + 8);
            cp16(smem_u32(&tn->Kp[lr][half*16]),   kpP);
            cp16(smem_u32(&tn->Kp[lr][half*16+8]), kpP + 8);
            cp16(smem_u32(&tn->Vh[lr][half*16]),   vhP);
            cp16(smem_u32(&tn->Vh[lr][half*16+8]), vhP + 8);
            if (tid < 8) cp16(smem_u32(&tn->lb[tid*8]), bP);
            CP_COMMIT();
            kP += 8192; kpP += 8192; vhP += 8192; bP += 256;
        }
        Tile& tb = tiles[cur];
        const uint32_t kb  = smem_u32(&tb.K [0][0]);
        const uint32_t kpb = smem_u32(&tb.Kp[0][0]);
        const uint32_t vhb = smem_u32(&tb.Vh[0][0]);

        const int  s0    = t * 64;
        const bool maskT = (t == nT - 1);

        #pragma unroll
        for (int h2 = 0; h2 < 2; h2++) {
            if (s0 + h2 * 32 > rmaxW) continue;   // fully-masked half (warp-uniform)
            uint32_t pAh[2][4];
            #pragma unroll
            for (int p = 0; p < 2; p++) {
                float4 S0 = make_float4(0.f,0.f,0.f,0.f), S1 = S0, C0 = S0, C1 = S0;
                const uint32_t rowoff = (uint32_t)(((h2 * 4 + p * 2 + g4hi) * 8 + i8) * 80);
                #pragma unroll
                for (int kk = 0; kk < 2; kk++) {
                    const uint32_t off = rowoff + kk * 32 + g4lo * 16;
                    uint32_t rB[4];
                    ldsm4(rB, kb + off);
                    mma16816(S0, qA[kk], rB[0], rB[1]);
                    mma16816(S1, qA[kk], rB[2], rB[3]);
                    ldsm4(rB, kpb + off);
                    mma16816(C0, pA_[kk], rB[0], rB[1]);
                    mma16816(C1, pA_[kk], rB[2], rB[3]);
                }
                // ---- packed fp16 epilogue: p = 2^( S * 2^(C + lb) ) ----
                #pragma unroll
                for (int q = 0; q < 2; q++) {
                    const float4 S = q ? S1 : S0;
                    const float4 C = q ? C1 : C0;
                    const int cl = (h2 * 4 + p * 2 + q) * 8 + 2 * tg;
                    const uint32_t lb2 = *(const uint32_t*)&tb.lb[cl];
                    uint32_t e01 = ex2h2(hadd2(pack2h(C.x, C.y), lb2));
                    uint32_t e23 = ex2h2(hadd2(pack2h(C.z, C.w), lb2));
                    uint32_t p01 = ex2h2(hmul2(pack2h(S.x, S.y), e01));
                    uint32_t p23 = ex2h2(hmul2(pack2h(S.z, S.w), e23));
                    if (maskT) {
                        const int cg = s0 + cl;
                        uint32_t mA = (cg <= r0g ? 0x3C00u : 0u) | (cg + 1 <= r0g ? 0x3C000000u : 0u);
                        uint32_t mB = (cg <= r1g ? 0x3C00u : 0u) | (cg + 1 <= r1g ? 0x3C000000u : 0u);
                        p01 = hmul2(p01, mA);
                        p23 = hmul2(p23, mB);
                    }
                    pAh[p][q * 2]     = p01;
                    pAh[p][q * 2 + 1] = p23;
                }
            }
            #pragma unroll
            for (int j2 = 0; j2 < 2; j2++) {
                const uint32_t srow = (uint32_t)((h2 * 32 + j2 * 16 + g4lo * 8 + i8) * 80);
                #pragma unroll
                for (int dp = 0; dp < 2; dp++) {
                    const uint32_t off = srow + (dp * 16 + g4hi * 8) * 2;
                    uint32_t vh[4];
                    ldsm4t(vh, vhb + off);
                    mma16816(O[dp*2],   pAh[j2], vh[0], vh[1]);
                    mma16816(O[dp*2+1], pAh[j2], vh[2], vh[3]);
                }
                mma16816(O5, pAh[j2], ONESH, ONESH);   // row-sum accumulator
            }
        }
    }

    // ---- write partials (no normalization here) ----
    float* o0 = &g_O[split][((size_t)bh * LLEN + r0g) * DD];
    float* o1 = &g_O[split][((size_t)bh * LLEN + r1g) * DD];
    #pragma unroll
    for (int dt = 0; dt < 4; dt++) {
        const int col = dt * 8 + 2 * tg;
        *(float2*)(o0 + col) = make_float2(O[dt].x, O[dt].y);
        *(float2*)(o1 + col) = make_float2(O[dt].z, O[dt].w);
    }
    if (tg == 0) {
        g_L[split][(size_t)bh * LLEN + r0g] = O5.x;
        g_L[split][(size_t)bh * LLEN + r1g] = O5.z;
    }
}

// ====== pass 3: combine partials, normalize, permute (8 threads per row) ======
__global__ void __launch_bounds__(256)
finalize(float* __restrict__ outg)
{
    const int idx = blockIdx.x * 256 + threadIdx.x;   // 262144 threads
    const int r = idx >> 3;              // row 0..32767 = bh*2048 + l
    const int j = idx & 7;               // float4 chunk
    const int bh = r >> 11, l = r & 2047;
    const int b = bh >> 3, h = bh & 7;
    const float rl = 1.f / (g_L[0][r] + g_L[1][r] + g_L[2][r] + g_L[3][r]);
    float4 x0 = ((const float4*)&g_O[0][(size_t)r * DD])[j];
    float4 x1 = ((const float4*)&g_O[1][(size_t)r * DD])[j];
    float4 x2 = ((const float4*)&g_O[2][(size_t)r * DD])[j];
    float4 x3 = ((const float4*)&g_O[3][(size_t)r * DD])[j];
    ((float4*)(outg + ((size_t)(b * LLEN + l) * HH + h) * DD))[j] =
        make_float4((x0.x + x1.x + x2.x + x3.x) * rl,
                    (x0.y + x1.y + x2.y + x3.y) * rl,
                    (x0.z + x1.z + x2.z + x3.z) * rl,
                    (x0.w + x1.w + x2.w + x3.w) * rl);
}

extern "C" void kernel_launch(void* const* d_in, const int* in_sizes, int n_in,
                              void* d_out, int out_size)
{
    const float* q = (const float*)d_in[0];
    const float* k = (const float*)d_in[1];
    const float* v = (const float*)d_in[2];

    preconvert<<<1024, 256>>>(k, v);

    cudaFuncSetAttribute(gauss_attn_mma9,
                         cudaFuncAttributeMaxDynamicSharedMemorySize, SMEM_BYTES);
    gauss_attn_mma9<<<2048, NTHR, SMEM_BYTES>>>(q);

    finalize<<<1024, 256>>>((float*)d_out);
}

// round 14
// speedup vs baseline: 1.0007x; 1.0007x over previous
#include <cuda_runtime.h>
#include <cuda_fp16.h>
#include <cstdint>

#define LLEN 2048
#define HH   8
#define EE   32
#define DD   32
#define NTHR 128
#define L2E  1.4426950408889634f

// ---- pre-converted fp16 operand arrays (filled by pass-1 kernel) ----
__device__ __half g_Kh [16 * 2048 * 32];
__device__ __half g_Kph[16 * 2048 * 32];
__device__ __half g_Vh [16 * 2048 * 32];
__device__ __half g_lbh[16 * 2048];            // half(-||k'||^2/32 * log2(e))
// ---- split-S partial accumulators (max 4 splits on heavy tiles) ----
__device__ float  g_O[4][16 * 2048 * 32];
__device__ float  g_L[4][16 * 2048];

struct Tile {                  // 80-byte row stride -> conflict-free ldmatrix
    __half K [64][40];
    __half Kp[64][40];
    __half Vh[64][40];
    __half lb[64];
};
#define SMEM_BYTES (2 * (int)sizeof(Tile))

__device__ __forceinline__ uint32_t smem_u32(const void* p) {
    uint32_t a;
    asm("{ .reg .u64 t; cvta.to.shared.u64 t, %1; cvt.u32.u64 %0, t; }"
        : "=r"(a) : "l"(p));
    return a;
}
__device__ __forceinline__ void cp16(uint32_t dst, const void* src) {
    asm volatile("cp.async.cg.shared.global [%0], [%1], 16;"
                 :: "r"(dst), "l"(src) : "memory");
}
#define CP_COMMIT() asm volatile("cp.async.commit_group;" ::: "memory")
#define CP_WAIT0()  asm volatile("cp.async.wait_group 0;" ::: "memory")

__device__ __forceinline__ void ldsm4(uint32_t* r, uint32_t a) {
    asm volatile("ldmatrix.sync.aligned.m8n8.x4.shared.b16 {%0,%1,%2,%3}, [%4];"
                 : "=r"(r[0]), "=r"(r[1]), "=r"(r[2]), "=r"(r[3]) : "r"(a));
}
__device__ __forceinline__ void ldsm4t(uint32_t* r, uint32_t a) {
    asm volatile("ldmatrix.sync.aligned.m8n8.x4.trans.shared.b16 {%0,%1,%2,%3}, [%4];"
                 : "=r"(r[0]), "=r"(r[1]), "=r"(r[2]), "=r"(r[3]) : "r"(a));
}
__device__ __forceinline__ void mma16816(float4& d, const uint32_t* a,
                                         uint32_t b0, uint32_t b1) {
    asm volatile(
        "mma.sync.aligned.m16n8k16.row.col.f32.f16.f16.f32 "
        "{%0,%1,%2,%3}, {%4,%5,%6,%7}, {%8,%9}, {%0,%1,%2,%3};"
        : "+f"(d.x), "+f"(d.y), "+f"(d.z), "+f"(d.w)
        : "r"(a[0]), "r"(a[1]), "r"(a[2]), "r"(a[3]), "r"(b0), "r"(b1));
}
__device__ __forceinline__ uint32_t pack2h(float x, float y) {
    __half2 h = __floats2half2_rn(x, y);
    return *reinterpret_cast<uint32_t*>(&h);
}
// ---- packed half2 epilogue ops ----
__device__ __forceinline__ uint32_t ex2h2(uint32_t x) {
    uint32_t r;
    asm("ex2.approx.f16x2 %0, %1;" : "=r"(r) : "r"(x));
    return r;
}
__device__ __forceinline__ uint32_t hadd2(uint32_t a, uint32_t b) {
    uint32_t r;
    asm("add.f16x2 %0, %1, %2;" : "=r"(r) : "r"(a), "r"(b));
    return r;
}
__device__ __forceinline__ uint32_t hmul2(uint32_t a, uint32_t b) {
    uint32_t r;
    asm("mul.f16x2 %0, %1, %2;" : "=r"(r) : "r"(a), "r"(b));
    return r;
}

// ========== pass 1: convert K, K', V to fp16 (8 threads per row) ==========
__global__ void __launch_bounds__(256)
preconvert(const float* __restrict__ kg, const float* __restrict__ vg)
{
    const int idx = blockIdx.x * 256 + threadIdx.x;   // 262144 threads
    const int rg  = idx >> 3;            // global row 0..32767
    const int j   = idx & 7;             // chunk within row
    const int r   = rg & 2047;
    const int bh  = rg >> 11;
    const int b   = bh >> 3, h = bh & 7;
    const float inv2 = 0.03125f;
    const size_t drow = (size_t)bh * LLEN + r;

    float4 tk = *(const float4*)(kg + ((size_t)(b * LLEN + r) * HH + h) * EE + 4 * j);
    const int rk = h * 256 + (r >> 3), hk = r & 7;
    float4 tp = *(const float4*)(kg + ((size_t)(b * LLEN + rk) * HH + hk) * EE + 4 * j);
    float4 tv = *(const float4*)(vg + ((size_t)(b * LLEN + r) * HH + h) * DD + 4 * j);

    *(uint2*)(g_Kh + drow * EE + 4 * j) =
        make_uint2(pack2h(tk.x, tk.y), pack2h(tk.z, tk.w));
    *(uint2*)(g_Kph + drow * EE + 4 * j) =
        make_uint2(pack2h(tp.x, tp.y), pack2h(tp.z, tp.w));
    float k2 = tp.x*tp.x + tp.y*tp.y + tp.z*tp.z + tp.w*tp.w;
    k2 += __shfl_xor_sync(0xffffffffu, k2, 1);
    k2 += __shfl_xor_sync(0xffffffffu, k2, 2);
    k2 += __shfl_xor_sync(0xffffffffu, k2, 4);
    if (j == 0) g_lbh[drow] = __float2half(-k2 * inv2 * L2E);
    *(uint2*)(g_Vh + drow * DD + 4 * j) =
        make_uint2(pack2h(tv.x, tv.y), pack2h(tv.z, tv.w));
}

// ========== main kernel: variable split depth per l-tile ==========
// bx [0,512):    lt 31..24, ns=4  (64 CTAs per lt)
// bx [512,1024): lt 23..8,  ns=2  (32 CTAs per lt)
// bx [1024,1152):lt 7..0,   ns=1  (16 CTAs per lt)
__global__ void __launch_bounds__(NTHR, 5)
gauss_attn_mma10(const float* __restrict__ qg)
{
    extern __shared__ Tile tiles[];   // [2]
    const int tid  = threadIdx.x;
    const int lane = tid & 31;
    const int wid  = tid >> 5;
    const int g    = lane >> 2;
    const int tg   = lane & 3;
    const int i8   = lane & 7;
    const int g4lo = (lane >> 3) & 1;
    const int g4hi = lane >> 4;

    const int bx = blockIdx.x;
    int lt, split, ns;
    if (bx < 512) {
        lt = 31 - (bx >> 6);  split = (bx >> 4) & 3;  ns = 4;
    } else if (bx < 1024) {
        const int y = bx - 512;
        lt = 23 - (y >> 5);   split = (y >> 4) & 1;   ns = 2;
    } else {
        const int y = bx - 1024;
        lt = 7 - (y >> 4);    split = 0;              ns = 1;
    }
    const int bh = bx & 15;
    const int b  = bh >> 3, h = bh & 7;
    const int l0 = lt * 64;
    const int nT = lt + 1;

    const float inv2 = 0.03125f;                   // 1/32
    const float inv3 = 0.005524271728019903f;      // 32^-1.5

    const int r0g = l0 + wid * 16 + g;
    const int r1g = r0g + 8;
    const int rmaxW = l0 + wid * 16 + 15;

    // ---- incremental gmem pointers (start at tile `split`, advance ns tiles) ----
    const int lr = tid >> 1, half = tid & 1;
    const int stepH = ns << 11;                    // ns*64 rows * 32 halves
    const int stepB = ns << 6;                     // ns*64 halves
    const size_t rowbase = ((size_t)bh * LLEN + split * 64 + lr) * EE + half * 16;
    const __half* kP  = g_Kh  + rowbase;
    const __half* kpP = g_Kph + rowbase;
    const __half* vhP = g_Vh  + rowbase;
    const __half* bP  = g_lbh + (size_t)bh * LLEN + split * 64 + tid * 8;

    if (split < nT) {
        Tile* tn = &tiles[0];
        cp16(smem_u32(&tn->K [lr][half*16]),   kP);
        cp16(smem_u32(&tn->K [lr][half*16+8]), kP  + 8);
        cp16(smem_u32(&tn->Kp[lr][half*16]),   kpP);
        cp16(smem_u32(&tn->Kp[lr][half*16+8]), kpP + 8);
        cp16(smem_u32(&tn->Vh[lr][half*16]),   vhP);
        cp16(smem_u32(&tn->Vh[lr][half*16+8]), vhP + 8);
        if (tid < 8) cp16(smem_u32(&tn->lb[tid*8]), bP);
        CP_COMMIT();
        kP += stepH; kpP += stepH; vhP += stepH; bP += stepB;
    }

    // ---- Q / Q' fragments: q2 first, then pack fp16 ----
    uint32_t qA[2][4], pA_[2][4];
    float q2r0 = 0.f, q2r1 = 0.f;
    {
        const int lq0 = h * 256 + (r0g >> 3), hq0 = r0g & 7;
        const int lq1 = h * 256 + (r1g >> 3), hq1 = r1g & 7;
        const float* s0p = qg + ((size_t)(b * LLEN + lq0) * HH + hq0) * EE + 2 * tg;
        const float* s1p = qg + ((size_t)(b * LLEN + lq1) * HH + hq1) * EE + 2 * tg;
        float2 t;
        #pragma unroll
        for (int c = 0; c < 4; c++) {
            t = *(const float2*)(s0p + 8 * c);  q2r0 += t.x*t.x + t.y*t.y;
            t = *(const float2*)(s1p + 8 * c);  q2r1 += t.x*t.x + t.y*t.y;
        }
        q2r0 += __shfl_xor_sync(0xffffffffu, q2r0, 1);
        q2r0 += __shfl_xor_sync(0xffffffffu, q2r0, 2);
        q2r1 += __shfl_xor_sync(0xffffffffu, q2r1, 1);
        q2r1 += __shfl_xor_sync(0xffffffffu, q2r1, 2);
        const float al0 = __expf(-q2r0 * inv2);    // alpha = exp(-||q'||^2/32)
        const float al1 = __expf(-q2r1 * inv2);
        const float sc0 = inv3 * L2E * al0;        // scale*log2e*alpha folded into Q
        const float sc1 = inv3 * L2E * al1;
        const float cs  = inv2 * 2.f * L2E;        // 2*log2e/32 folded into Q'

        const float* p0 = qg + ((size_t)(b * LLEN + r0g) * HH + h) * EE + 2 * tg;
        const float* p1 = qg + ((size_t)(b * LLEN + r1g) * HH + h) * EE + 2 * tg;
        #pragma unroll
        for (int kk = 0; kk < 2; kk++) {
            t = *(const float2*)(p0 + 16*kk);      qA[kk][0] = pack2h(t.x*sc0, t.y*sc0);
            t = *(const float2*)(p1 + 16*kk);      qA[kk][1] = pack2h(t.x*sc1, t.y*sc1);
            t = *(const float2*)(p0 + 16*kk + 8);  qA[kk][2] = pack2h(t.x*sc0, t.y*sc0);
            t = *(const float2*)(p1 + 16*kk + 8);  qA[kk][3] = pack2h(t.x*sc1, t.y*sc1);
            t = *(const float2*)(s0p + 16*kk);     pA_[kk][0] = pack2h(t.x*cs, t.y*cs);
            t = *(const float2*)(s1p + 16*kk);     pA_[kk][1] = pack2h(t.x*cs, t.y*cs);
            t = *(const float2*)(s0p + 16*kk + 8); pA_[kk][2] = pack2h(t.x*cs, t.y*cs);
            t = *(const float2*)(s1p + 16*kk + 8); pA_[kk][3] = pack2h(t.x*cs, t.y*cs);
        }
    }
    const uint32_t ONESH = pack2h(1.f, 1.f);

    float4 O[4], O5;
    #pragma unroll
    for (int i = 0; i < 4; i++) O[i] = make_float4(0.f, 0.f, 0.f, 0.f);
    O5 = make_float4(0.f, 0.f, 0.f, 0.f);

    int it = 0;
    for (int t = split; t < nT; t += ns, it++) {
        const int cur = it & 1;
        CP_WAIT0();
        __syncthreads();
        if (t + ns < nT) {
            Tile* tn = &tiles[cur ^ 1];
            cp16(smem_u32(&tn->K [lr][half*16]),   kP);
            cp16(smem_u32(&tn->K [lr][half*16+8]), kP  + 8);
            cp16(smem_u32(&tn->Kp[lr][half*16]),   kpP);
            cp16(smem_u32(&tn->Kp[lr][half*16+8]), kpP + 8);
            cp16(smem_u32(&tn->Vh[lr][half*16]),   vhP);
            cp16(smem_u32(&tn->Vh[lr][half*16+8]), vhP + 8);
            if (tid < 8) cp16(smem_u32(&tn->lb[tid*8]), bP);
            CP_COMMIT();
            kP += stepH; kpP += stepH; vhP += stepH; bP += stepB;
        }
        Tile& tb = tiles[cur];
        const uint32_t kb  = smem_u32(&tb.K [0][0]);
        const uint32_t kpb = smem_u32(&tb.Kp[0][0]);
        const uint32_t vhb = smem_u32(&tb.Vh[0][0]);

        const int  s0    = t * 64;
        const bool maskT = (t == nT - 1);

        #pragma unroll
        for (int h2 = 0; h2 < 2; h2++) {
            if (s0 + h2 * 32 > rmaxW) continue;   // fully-masked half (warp-uniform)
            uint32_t pAh[2][4];
            #pragma unroll
            for (int p = 0; p < 2; p++) {
                float4 S0 = make_float4(0.f,0.f,0.f,0.f), S1 = S0, C0 = S0, C1 = S0;
                const uint32_t rowoff = (uint32_t)(((h2 * 4 + p * 2 + g4hi) * 8 + i8) * 80);
                #pragma unroll
                for (int kk = 0; kk < 2; kk++) {
                    const uint32_t off = rowoff + kk * 32 + g4lo * 16;
                    uint32_t rB[4];
                    ldsm4(rB, kb + off);
                    mma16816(S0, qA[kk], rB[0], rB[1]);
                    mma16816(S1, qA[kk], rB[2], rB[3]);
                    ldsm4(rB, kpb + off);
                    mma16816(C0, pA_[kk], rB[0], rB[1]);
                    mma16816(C1, pA_[kk], rB[2], rB[3]);
                }
                // ---- packed fp16 epilogue: p = 2^( S * 2^(C + lb) ) ----
                #pragma unroll
                for (int q = 0; q < 2; q++) {
                    const float4 S = q ? S1 : S0;
                    const float4 C = q ? C1 : C0;
                    const int cl = (h2 * 4 + p * 2 + q) * 8 + 2 * tg;
                    const uint32_t lb2 = *(const uint32_t*)&tb.lb[cl];
                    uint32_t e01 = ex2h2(hadd2(pack2h(C.x, C.y), lb2));
                    uint32_t e23 = ex2h2(hadd2(pack2h(C.z, C.w), lb2));
                    uint32_t p01 = ex2h2(hmul2(pack2h(S.x, S.y), e01));
                    uint32_t p23 = ex2h2(hmul2(pack2h(S.z, S.w), e23));
                    if (maskT) {
                        const int cg = s0 + cl;
                        uint32_t mA = (cg <= r0g ? 0x3C00u : 0u) | (cg + 1 <= r0g ? 0x3C000000u : 0u);
                        uint32_t mB = (cg <= r1g ? 0x3C00u : 0u) | (cg + 1 <= r1g ? 0x3C000000u : 0u);
                        p01 = hmul2(p01, mA);
                        p23 = hmul2(p23, mB);
                    }
                    pAh[p][q * 2]     = p01;
                    pAh[p][q * 2 + 1] = p23;
                }
            }
            #pragma unroll
            for (int j2 = 0; j2 < 2; j2++) {
                const uint32_t srow = (uint32_t)((h2 * 32 + j2 * 16 + g4lo * 8 + i8) * 80);
                #pragma unroll
                for (int dp = 0; dp < 2; dp++) {
                    const uint32_t off = srow + (dp * 16 + g4hi * 8) * 2;
                    uint32_t vh[4];
                    ldsm4t(vh, vhb + off);
                    mma16816(O[dp*2],   pAh[j2], vh[0], vh[1]);
                    mma16816(O[dp*2+1], pAh[j2], vh[2], vh[3]);
                }
                mma16816(O5, pAh[j2], ONESH, ONESH);   // row-sum accumulator
            }
        }
    }

    // ---- write partials (no normalization here) ----
    float* o0 = &g_O[split][((size_t)bh * LLEN + r0g) * DD];
    float* o1 = &g_O[split][((size_t)bh * LLEN + r1g) * DD];
    #pragma unroll
    for (int dt = 0; dt < 4; dt++) {
        const int col = dt * 8 + 2 * tg;
        *(float2*)(o0 + col) = make_float2(O[dt].x, O[dt].y);
        *(float2*)(o1 + col) = make_float2(O[dt].z, O[dt].w);
    }
    if (tg == 0) {
        g_L[split][(size_t)bh * LLEN + r0g] = O5.x;
        g_L[split][(size_t)bh * LLEN + r1g] = O5.z;
    }
}

// ====== pass 3: combine live partials (count depends on l-tile), normalize ======
__global__ void __launch_bounds__(256)
finalize(float* __restrict__ outg)
{
    const int idx = blockIdx.x * 256 + threadIdx.x;   // 262144 threads
    const int r = idx >> 3;              // row 0..32767 = bh*2048 + l
    const int j = idx & 7;               // float4 chunk
    const int bh = r >> 11, l = r & 2047;
    const int b = bh >> 3, h = bh & 7;
    const int lt = l >> 6;
    const int ns = (lt >= 24) ? 4 : (lt >= 8) ? 2 : 1;

    float L = g_L[0][r];
    float4 s = ((const float4*)&g_O[0][(size_t)r * DD])[j];
    if (ns >= 2) {
        L += g_L[1][r];
        float4 x = ((const float4*)&g_O[1][(size_t)r * DD])[j];
        s.x += x.x; s.y += x.y; s.z += x.z; s.w += x.w;
    }
    if (ns == 4) {
        L += g_L[2][r] + g_L[3][r];
        float4 x = ((const float4*)&g_O[2][(size_t)r * DD])[j];
        float4 y = ((const float4*)&g_O[3][(size_t)r * DD])[j];
        s.x += x.x + y.x; s.y += x.y + y.y;
        s.z += x.z + y.z; s.w += x.w + y.w;
    }
    const float rl = 1.f / L;
    ((float4*)(outg + ((size_t)(b * LLEN + l) * HH + h) * DD))[j] =
        make_float4(s.x * rl, s.y * rl, s.z * rl, s.w * rl);
}

extern "C" void kernel_launch(void* const* d_in, const int* in_sizes, int n_in,
                              void* d_out, int out_size)
{
    const float* q = (const float*)d_in[0];
    const float* k = (const float*)d_in[1];
    const float* v = (const float*)d_in[2];

    preconvert<<<1024, 256>>>(k, v);

    cudaFuncSetAttribute(gauss_attn_mma10,
                         cudaFuncAttributeMaxDynamicSharedMemorySize, SMEM_BYTES);
    gauss_attn_mma10<<<1152, NTHR, SMEM_BYTES>>>(q);

    finalize<<<1024, 256>>>((float*)d_out);
}

// round 16
// speedup vs baseline: 1.0428x; 1.0421x over previous
#include <cuda_runtime.h>
#include <cuda_fp16.h>
#include <cstdint>

#define LLEN 2048
#define HH   8
#define EE   32
#define DD   32
#define NTHR 128
#define L2E  1.4426950408889634f

// ---- pre-converted fp16 operand arrays (filled by pass-1 kernel) ----
__device__ __half g_Kh [16 * 2048 * 32];
__device__ __half g_Kph[16 * 2048 * 32];
__device__ __half g_Vh [16 * 2048 * 32];
__device__ __half g_lbh[16 * 2048];            // half(-||k'||^2/32 * log2(e))
// ---- split-S partial accumulators ----
__device__ float  g_O[2][16 * 2048 * 32];
__device__ float  g_L[2][16 * 2048];

struct Tile {                  // 80-byte row stride -> conflict-free ldmatrix
    __half K [64][40];
    __half Kp[64][40];
    __half Vh[64][40];
    __half lb[64];
};
#define SMEM_BYTES (2 * (int)sizeof(Tile))

__device__ __forceinline__ uint32_t smem_u32(const void* p) {
    uint32_t a;
    asm("{ .reg .u64 t; cvta.to.shared.u64 t, %1; cvt.u32.u64 %0, t; }"
        : "=r"(a) : "l"(p));
    return a;
}
__device__ __forceinline__ void cp16(uint32_t dst, const void* src) {
    asm volatile("cp.async.cg.shared.global [%0], [%1], 16;"
                 :: "r"(dst), "l"(src) : "memory");
}
#define CP_COMMIT() asm volatile("cp.async.commit_group;" ::: "memory")
#define CP_WAIT0()  asm volatile("cp.async.wait_group 0;" ::: "memory")

__device__ __forceinline__ void ldsm4(uint32_t* r, uint32_t a) {
    asm volatile("ldmatrix.sync.aligned.m8n8.x4.shared.b16 {%0,%1,%2,%3}, [%4];"
                 : "=r"(r[0]), "=r"(r[1]), "=r"(r[2]), "=r"(r[3]) : "r"(a));
}
__device__ __forceinline__ void ldsm4t(uint32_t* r, uint32_t a) {
    asm volatile("ldmatrix.sync.aligned.m8n8.x4.trans.shared.b16 {%0,%1,%2,%3}, [%4];"
                 : "=r"(r[0]), "=r"(r[1]), "=r"(r[2]), "=r"(r[3]) : "r"(a));
}
__device__ __forceinline__ void mma16816(float4& d, const uint32_t* a,
                                         uint32_t b0, uint32_t b1) {
    asm volatile(
        "mma.sync.aligned.m16n8k16.row.col.f32.f16.f16.f32 "
        "{%0,%1,%2,%3}, {%4,%5,%6,%7}, {%8,%9}, {%0,%1,%2,%3};"
        : "+f"(d.x), "+f"(d.y), "+f"(d.z), "+f"(d.w)
        : "r"(a[0]), "r"(a[1]), "r"(a[2]), "r"(a[3]), "r"(b0), "r"(b1));
}
__device__ __forceinline__ uint32_t pack2h(float x, float y) {
    __half2 h = __floats2half2_rn(x, y);
    return *reinterpret_cast<uint32_t*>(&h);
}
// ---- packed half2 epilogue ops ----
__device__ __forceinline__ uint32_t ex2h2(uint32_t x) {
    uint32_t r;
    asm("ex2.approx.f16x2 %0, %1;" : "=r"(r) : "r"(x));
    return r;
}
__device__ __forceinline__ uint32_t hadd2(uint32_t a, uint32_t b) {
    uint32_t r;
    asm("add.f16x2 %0, %1, %2;" : "=r"(r) : "r"(a), "r"(b));
    return r;
}
__device__ __forceinline__ uint32_t hmul2(uint32_t a, uint32_t b) {
    uint32_t r;
    asm("mul.f16x2 %0, %1, %2;" : "=r"(r) : "r"(a), "r"(b));
    return r;
}

// ========== pass 1: convert K, K', V to fp16 (8 threads per row) ==========
__global__ void __launch_bounds__(256)
preconvert(const float* __restrict__ kg, const float* __restrict__ vg)
{
    const int idx = blockIdx.x * 256 + threadIdx.x;   // 262144 threads
    const int rg  = idx >> 3;            // global row 0..32767
    const int j   = idx & 7;             // chunk within row
    const int r   = rg & 2047;
    const int bh  = rg >> 11;
    const int b   = bh >> 3, h = bh & 7;
    const float inv2 = 0.03125f;
    const size_t drow = (size_t)bh * LLEN + r;

    float4 tk = *(const float4*)(kg + ((size_t)(b * LLEN + r) * HH + h) * EE + 4 * j);
    const int rk = h * 256 + (r >> 3), hk = r & 7;
    float4 tp = *(const float4*)(kg + ((size_t)(b * LLEN + rk) * HH + hk) * EE + 4 * j);
    float4 tv = *(const float4*)(vg + ((size_t)(b * LLEN + r) * HH + h) * DD + 4 * j);

    *(uint2*)(g_Kh + drow * EE + 4 * j) =
        make_uint2(pack2h(tk.x, tk.y), pack2h(tk.z, tk.w));
    *(uint2*)(g_Kph + drow * EE + 4 * j) =
        make_uint2(pack2h(tp.x, tp.y), pack2h(tp.z, tp.w));
    float k2 = tp.x*tp.x + tp.y*tp.y + tp.z*tp.z + tp.w*tp.w;
    k2 += __shfl_xor_sync(0xffffffffu, k2, 1);
    k2 += __shfl_xor_sync(0xffffffffu, k2, 2);
    k2 += __shfl_xor_sync(0xffffffffu, k2, 4);
    if (j == 0) g_lbh[drow] = __float2half(-k2 * inv2 * L2E);
    *(uint2*)(g_Vh + drow * DD + 4 * j) =
        make_uint2(pack2h(tv.x, tv.y), pack2h(tv.z, tv.w));
}

// ================= main kernel (split-S, 2 CTAs per l-tile) =================
__global__ void __launch_bounds__(NTHR, 5)
gauss_attn_mma11(const float* __restrict__ qg)
{
    extern __shared__ Tile tiles[];   // [2]
    const int tid  = threadIdx.x;
    const int lane = tid & 31;
    const int wid  = tid >> 5;
    const int g    = lane >> 2;
    const int tg   = lane & 3;
    const int i8   = lane & 7;
    const int g4lo = (lane >> 3) & 1;
    const int g4hi = lane >> 4;

    const int bx    = blockIdx.x;               // 1024 CTAs
    const int bh    = bx & 15;
    const int split = (bx >> 4) & 1;
    const int u     = bx >> 5;
    const int lt    = (u & 1) ? (u >> 1) : (31 - (u >> 1));   // interleaved heavy/light
    const int b     = bh >> 3, h = bh & 7;
    const int l0    = lt * 64;
    const int nT    = lt + 1;

    const float inv2 = 0.03125f;                   // 1/32
    const float inv3 = 0.005524271728019903f;      // 32^-1.5

    const int r0g = l0 + wid * 16 + g;
    const int r1g = r0g + 8;
    const int rmaxW = l0 + wid * 16 + 15;

    // ---- incremental gmem pointers (start at tile `split`, advance 2 tiles) ----
    const int lr = tid >> 1, half = tid & 1;
    const size_t rowbase = ((size_t)bh * LLEN + split * 64 + lr) * EE + half * 16;
    const __half* kP  = g_Kh  + rowbase;
    const __half* kpP = g_Kph + rowbase;
    const __half* vhP = g_Vh  + rowbase;
    const __half* bP  = g_lbh + (size_t)bh * LLEN + split * 64 + tid * 8;

    if (split < nT) {
        Tile* tn = &tiles[0];
        cp16(smem_u32(&tn->K [lr][half*16]),   kP);
        cp16(smem_u32(&tn->K [lr][half*16+8]), kP  + 8);
        cp16(smem_u32(&tn->Kp[lr][half*16]),   kpP);
        cp16(smem_u32(&tn->Kp[lr][half*16+8]), kpP + 8);
        cp16(smem_u32(&tn->Vh[lr][half*16]),   vhP);
        cp16(smem_u32(&tn->Vh[lr][half*16+8]), vhP + 8);
        if (tid < 8) cp16(smem_u32(&tn->lb[tid*8]), bP);
        CP_COMMIT();
        kP += 4096; kpP += 4096; vhP += 4096; bP += 128;
    }

    // ---- Q / Q' fragments: q2 first, then pack fp16 ----
    uint32_t qA[2][4], pA_[2][4];
    float q2r0 = 0.f, q2r1 = 0.f;
    {
        const int lq0 = h * 256 + (r0g >> 3), hq0 = r0g & 7;
        const int lq1 = h * 256 + (r1g >> 3), hq1 = r1g & 7;
        const float* s0p = qg + ((size_t)(b * LLEN + lq0) * HH + hq0) * EE + 2 * tg;
        const float* s1p = qg + ((size_t)(b * LLEN + lq1) * HH + hq1) * EE + 2 * tg;
        float2 t;
        #pragma unroll
        for (int c = 0; c < 4; c++) {
            t = *(const float2*)(s0p + 8 * c);  q2r0 += t.x*t.x + t.y*t.y;
            t = *(const float2*)(s1p + 8 * c);  q2r1 += t.x*t.x + t.y*t.y;
        }
        q2r0 += __shfl_xor_sync(0xffffffffu, q2r0, 1);
        q2r0 += __shfl_xor_sync(0xffffffffu, q2r0, 2);
        q2r1 += __shfl_xor_sync(0xffffffffu, q2r1, 1);
        q2r1 += __shfl_xor_sync(0xffffffffu, q2r1, 2);
        const float al0 = __expf(-q2r0 * inv2);    // alpha = exp(-||q'||^2/32)
        const float al1 = __expf(-q2r1 * inv2);
        const float sc0 = inv3 * L2E * al0;        // scale*log2e*alpha folded into Q
        const float sc1 = inv3 * L2E * al1;
        const float cs  = inv2 * 2.f * L2E;        // 2*log2e/32 folded into Q'

        const float* p0 = qg + ((size_t)(b * LLEN + r0g) * HH + h) * EE + 2 * tg;
        const float* p1 = qg + ((size_t)(b * LLEN + r1g) * HH + h) * EE + 2 * tg;
        #pragma unroll
        for (int kk = 0; kk < 2; kk++) {
            t = *(const float2*)(p0 + 16*kk);      qA[kk][0] = pack2h(t.x*sc0, t.y*sc0);
            t = *(const float2*)(p1 + 16*kk);      qA[kk][1] = pack2h(t.x*sc1, t.y*sc1);
            t = *(const float2*)(p0 + 16*kk + 8);  qA[kk][2] = pack2h(t.x*sc0, t.y*sc0);
            t = *(const float2*)(p1 + 16*kk + 8);  qA[kk][3] = pack2h(t.x*sc1, t.y*sc1);
            t = *(const float2*)(s0p + 16*kk);     pA_[kk][0] = pack2h(t.x*cs, t.y*cs);
            t = *(const float2*)(s1p + 16*kk);     pA_[kk][1] = pack2h(t.x*cs, t.y*cs);
            t = *(const float2*)(s0p + 16*kk + 8); pA_[kk][2] = pack2h(t.x*cs, t.y*cs);
            t = *(const float2*)(s1p + 16*kk + 8); pA_[kk][3] = pack2h(t.x*cs, t.y*cs);
        }
    }
    const uint32_t ONESH = pack2h(1.f, 1.f);

    float4 O[4], O5;
    #pragma unroll
    for (int i = 0; i < 4; i++) O[i] = make_float4(0.f, 0.f, 0.f, 0.f);
    O5 = make_float4(0.f, 0.f, 0.f, 0.f);

    int it = 0;
    for (int t = split; t < nT; t += 2, it++) {
        const int cur = it & 1;
        CP_WAIT0();
        __syncthreads();
        if (t + 2 < nT) {
            Tile* tn = &tiles[cur ^ 1];
            cp16(smem_u32(&tn->K [lr][half*16]),   kP);
            cp16(smem_u32(&tn->K [lr][half*16+8]), kP  + 8);
            cp16(smem_u32(&tn->Kp[lr][half*16]),   kpP);
            cp16(smem_u32(&tn->Kp[lr][half*16+8]), kpP + 8);
            cp16(smem_u32(&tn->Vh[lr][half*16]),   vhP);
            cp16(smem_u32(&tn->Vh[lr][half*16+8]), vhP + 8);
            if (tid < 8) cp16(smem_u32(&tn->lb[tid*8]), bP);
            CP_COMMIT();
            kP += 4096; kpP += 4096; vhP += 4096; bP += 128;
        }
        Tile& tb = tiles[cur];
        const uint32_t kb  = smem_u32(&tb.K [0][0]);
        const uint32_t kpb = smem_u32(&tb.Kp[0][0]);
        const uint32_t vhb = smem_u32(&tb.Vh[0][0]);

        const int  s0    = t * 64;
        const bool maskT = (t == nT - 1);

        #pragma unroll
        for (int h2 = 0; h2 < 2; h2++) {
            if (s0 + h2 * 32 > rmaxW) continue;   // fully-masked half (warp-uniform)
            // ---- wide phase: all 16 S/C MMAs issued back-to-back ----
            float4 S[4], C[4];
            #pragma unroll
            for (int i = 0; i < 4; i++) {
                S[i] = make_float4(0.f, 0.f, 0.f, 0.f);
                C[i] = make_float4(0.f, 0.f, 0.f, 0.f);
            }
            #pragma unroll
            for (int p = 0; p < 2; p++) {
                const uint32_t rowoff = (uint32_t)(((h2 * 4 + p * 2 + g4hi) * 8 + i8) * 80);
                #pragma unroll
                for (int kk = 0; kk < 2; kk++) {
                    const uint32_t off = rowoff + kk * 32 + g4lo * 16;
                    uint32_t rB[4];
                    ldsm4(rB, kb + off);
                    mma16816(S[p*2],   qA[kk], rB[0], rB[1]);
                    mma16816(S[p*2+1], qA[kk], rB[2], rB[3]);
                    ldsm4(rB, kpb + off);
                    mma16816(C[p*2],   pA_[kk], rB[0], rB[1]);
                    mma16816(C[p*2+1], pA_[kk], rB[2], rB[3]);
                }
            }
            // ---- packed fp16 epilogue: p = 2^( S * 2^(C + lb) ) ----
            uint32_t pAh[2][4];
            #pragma unroll
            for (int nt4 = 0; nt4 < 4; nt4++) {
                const int cl = (h2 * 4 + nt4) * 8 + 2 * tg;
                const uint32_t lb2 = *(const uint32_t*)&tb.lb[cl];
                uint32_t e01 = ex2h2(hadd2(pack2h(C[nt4].x, C[nt4].y), lb2));
                uint32_t e23 = ex2h2(hadd2(pack2h(C[nt4].z, C[nt4].w), lb2));
                uint32_t p01 = ex2h2(hmul2(pack2h(S[nt4].x, S[nt4].y), e01));
                uint32_t p23 = ex2h2(hmul2(pack2h(S[nt4].z, S[nt4].w), e23));
                if (maskT) {
                    const int cg = s0 + cl;
                    uint32_t mA = (cg <= r0g ? 0x3C00u : 0u) | (cg + 1 <= r0g ? 0x3C000000u : 0u);
                    uint32_t mB = (cg <= r1g ? 0x3C00u : 0u) | (cg + 1 <= r1g ? 0x3C000000u : 0u);
                    p01 = hmul2(p01, mA);
                    p23 = hmul2(p23, mB);
                }
                pAh[nt4 >> 1][(nt4 & 1) * 2]     = p01;
                pAh[nt4 >> 1][(nt4 & 1) * 2 + 1] = p23;
            }
            // ---- O += P V ; row sums via ones-column MMA ----
            #pragma unroll
            for (int j2 = 0; j2 < 2; j2++) {
                const uint32_t srow = (uint32_t)((h2 * 32 + j2 * 16 + g4lo * 8 + i8) * 80);
                #pragma unroll
                for (int dp = 0; dp < 2; dp++) {
                    const uint32_t off = srow + (dp * 16 + g4hi * 8) * 2;
                    uint32_t vh[4];
                    ldsm4t(vh, vhb + off);
                    mma16816(O[dp*2],   pAh[j2], vh[0], vh[1]);
                    mma16816(O[dp*2+1], pAh[j2], vh[2], vh[3]);
                }
                mma16816(O5, pAh[j2], ONESH, ONESH);   // row-sum accumulator
            }
        }
    }

    // ---- write partials (no normalization here) ----
    float* o0 = &g_O[split][((size_t)bh * LLEN + r0g) * DD];
    float* o1 = &g_O[split][((size_t)bh * LLEN + r1g) * DD];
    #pragma unroll
    for (int dt = 0; dt < 4; dt++) {
        const int col = dt * 8 + 2 * tg;
        *(float2*)(o0 + col) = make_float2(O[dt].x, O[dt].y);
        *(float2*)(o1 + col) = make_float2(O[dt].z, O[dt].w);
    }
    if (tg == 0) {
        g_L[split][(size_t)bh * LLEN + r0g] = O5.x;
        g_L[split][(size_t)bh * LLEN + r1g] = O5.z;
    }
}

// ====== pass 3: combine partials, normalize, permute (8 threads per row) ======
__global__ void __launch_bounds__(256)
finalize(float* __restrict__ outg)
{
    const int idx = blockIdx.x * 256 + threadIdx.x;   // 262144 threads
    const int r = idx >> 3;              // row 0..32767 = bh*2048 + l
    const int j = idx & 7;               // float4 chunk
    const int bh = r >> 11, l = r & 2047;
    const int b = bh >> 3, h = bh & 7;
    const float rl = 1.f / (g_L[0][r] + g_L[1][r]);
    float4 x = ((const float4*)&g_O[0][(size_t)r * DD])[j];
    float4 y = ((const float4*)&g_O[1][(size_t)r * DD])[j];
    ((float4*)(outg + ((size_t)(b * LLEN + l) * HH + h) * DD))[j] =
        make_float4((x.x + y.x) * rl, (x.y + y.y) * rl,
                    (x.z + y.z) * rl, (x.w + y.w) * rl);
}

extern "C" void kernel_launch(void* const* d_in, const int* in_sizes, int n_in,
                              void* d_out, int out_size)
{
    const float* q = (const float*)d_in[0];
    const float* k = (const float*)d_in[1];
    const float* v = (const float*)d_in[2];

    preconvert<<<1024, 256>>>(k, v);

    cudaFuncSetAttribute(gauss_attn_mma11,
                         cudaFuncAttributeMaxDynamicSharedMemorySize, SMEM_BYTES);
    gauss_attn_mma11<<<1024, NTHR, SMEM_BYTES>>>(q);

    finalize<<<1024, 256>>>((float*)d_out);
}